// round 15
// baseline (speedup 1.0000x reference)
#include <cuda_runtime.h>
#include <cuda_bf16.h>
#include <mma.h>
#include <cstdint>

using namespace nvcuda;

#define B_   16
#define CH_  64
#define TOK  16384
#define CNT  (16.0f*16384.0f)

__device__ float g_XT[B_*TOK*CH_];
__device__ float g_V [B_*TOK*CH_];
__device__ float g_C    [B_*64*64];
__device__ float g_Weff [B_*64*64];
__device__ float g_stats[256];
__device__ float g_pooled[B_*64*64];
__device__ float g_minmax[2];
__device__ float g_gate[B_*64];

__device__ __forceinline__ float leaky(float x){ return x >= 0.f ? x : 0.2f*x; }
__device__ __forceinline__ void split_bf16(float f, __nv_bfloat16& h, __nv_bfloat16& l){
  h = __float2bfloat16_rn(f);
  l = __float2bfloat16_rn(f - __bfloat162float(h));
}

// ---------------- NCHW -> BHWC transpose ----------------
__global__ void k_transpose_in(const float* __restrict__ x){
  int b = blockIdx.x, n0 = blockIdx.y * 64;
  __shared__ float s[64*65];
  const float* xb = x + (size_t)b*CH_*TOK;
  for (int idx = threadIdx.x; idx < 4096; idx += 256){
    int c = idx >> 6, j = idx & 63;
    s[c*65 + j] = xb[(size_t)c*TOK + n0 + j];
  }
  __syncthreads();
  float* xt = g_XT + ((size_t)b*TOK + n0)*CH_;
  for (int idx = threadIdx.x; idx < 4096; idx += 256){
    int j = idx >> 6, c = idx & 63;
    xt[j*CH_ + c] = s[c*65 + j];
  }
}

// =============== wmma GEMM — slim smem (R14 verbatim) ===============
// MODE 0: V = XT @ W (direct global store) + FUSED gram partial
// MODE 3: V = BN1(leaky(XT)) @ W ; leaky stats -> g_stats[128..255]
#define SM_GEMM_BYTES 55296
template<int MODE>
__global__ __launch_bounds__(256)
void k_gemm(const float* __restrict__ W, const float* __restrict__ aux0,
            const float* __restrict__ aux1){
  extern __shared__ unsigned char smraw[];
  __nv_bfloat16* Ah = (__nv_bfloat16*)smraw;
  __nv_bfloat16* Al = (__nv_bfloat16*)(smraw + 18432);
  __nv_bfloat16* Bh = (__nv_bfloat16*)(smraw + 36864);
  __nv_bfloat16* Bl = (__nv_bfloat16*)(smraw + 46080);
  float* outF = (float*)smraw;
  __shared__ float s_a[64], s_b[64];
  __shared__ float red[512];

  int tid = threadIdx.x, wid = tid >> 5;
  int b = blockIdx.x, n0 = blockIdx.y * 128;
  int m0 = wid * 16;

  if (MODE == 3 && tid < 64){
    float m   = g_stats[tid]      * (1.f/CNT);
    float var = g_stats[64 + tid] * (1.f/CNT) - m*m;
    float sc  = aux0[tid] * rsqrtf(var + 1e-4f);
    s_a[tid] = sc; s_b[tid] = aux1[tid] - m*sc;
  }

  const float4* W4 = (const float4*)W;
  for (int i = tid; i < 1024; i += 256){
    float4 v = W4[i];
    int k = i >> 4, n = (i & 15) * 4;
    __nv_bfloat16 h, l;
    split_bf16(v.x, h, l); Bh[k*72+n  ] = h; Bl[k*72+n  ] = l;
    split_bf16(v.y, h, l); Bh[k*72+n+1] = h; Bl[k*72+n+1] = l;
    split_bf16(v.z, h, l); Bh[k*72+n+2] = h; Bl[k*72+n+2] = l;
    split_bf16(v.w, h, l); Bh[k*72+n+3] = h; Bl[k*72+n+3] = l;
  }
  __syncthreads();

  const float4* IN4 = (const float4*)(g_XT + ((size_t)b*TOK + n0)*CH_);
  for (int i = tid; i < 2048; i += 256){
    float4 v = IN4[i];
    int t = i >> 4, c = (i & 15) * 4;
    float f0 = v.x, f1 = v.y, f2 = v.z, f3 = v.w;
    if (MODE == 3){
      f0 = leaky(f0)*s_a[c  ] + s_b[c  ];
      f1 = leaky(f1)*s_a[c+1] + s_b[c+1];
      f2 = leaky(f2)*s_a[c+2] + s_b[c+2];
      f3 = leaky(f3)*s_a[c+3] + s_b[c+3];
    }
    __nv_bfloat16 h, l;
    split_bf16(f0, h, l); Ah[t*72+c  ] = h; Al[t*72+c  ] = l;
    split_bf16(f1, h, l); Ah[t*72+c+1] = h; Al[t*72+c+1] = l;
    split_bf16(f2, h, l); Ah[t*72+c+2] = h; Al[t*72+c+2] = l;
    split_bf16(f3, h, l); Ah[t*72+c+3] = h; Al[t*72+c+3] = l;
  }
  __syncthreads();

  {
    wmma::fragment<wmma::accumulator,16,16,16,float> acc[4];
#pragma unroll
    for (int j = 0; j < 4; j++) wmma::fill_fragment(acc[j], 0.f);
#pragma unroll
    for (int k = 0; k < 4; k++){
      wmma::fragment<wmma::matrix_a,16,16,16,__nv_bfloat16,wmma::row_major> ah, al;
      wmma::load_matrix_sync(ah, Ah + m0*72 + k*16, 72);
      wmma::load_matrix_sync(al, Al + m0*72 + k*16, 72);
#pragma unroll
      for (int j = 0; j < 4; j++){
        wmma::fragment<wmma::matrix_b,16,16,16,__nv_bfloat16,wmma::row_major> bh, bl;
        wmma::load_matrix_sync(bh, Bh + (k*16)*72 + j*16, 72);
        wmma::load_matrix_sync(bl, Bl + (k*16)*72 + j*16, 72);
        wmma::mma_sync(acc[j], ah, bh, acc[j]);
        wmma::mma_sync(acc[j], ah, bl, acc[j]);
        wmma::mma_sync(acc[j], al, bh, acc[j]);
      }
    }
    if (MODE == 0){
      float* O = g_V + ((size_t)b*TOK + n0 + m0)*CH_;
#pragma unroll
      for (int j = 0; j < 4; j++)
        wmma::store_matrix_sync(O + j*16, acc[j], 64, wmma::mem_row_major);
    } else {
      __syncthreads();
#pragma unroll
      for (int j = 0; j < 4; j++)
        wmma::store_matrix_sync(outF + m0*68 + j*16, acc[j], 68, wmma::mem_row_major);
    }
  }

  if (MODE == 0){
    int mwid = wid & 3, nh = wid >> 2;
    int mg = mwid * 16, j0 = nh * 2;
    wmma::fragment<wmma::accumulator,16,16,16,float> acc2[2];
#pragma unroll
    for (int j = 0; j < 2; j++) wmma::fill_fragment(acc2[j], 0.f);
#pragma unroll
    for (int k = 0; k < 8; k++){
      wmma::fragment<wmma::matrix_a,16,16,16,__nv_bfloat16,wmma::col_major> ah, al;
      wmma::load_matrix_sync(ah, Ah + (k*16)*72 + mg, 72);
      wmma::load_matrix_sync(al, Al + (k*16)*72 + mg, 72);
#pragma unroll
      for (int jj = 0; jj < 2; jj++){
        int j = j0 + jj;
        wmma::fragment<wmma::matrix_b,16,16,16,__nv_bfloat16,wmma::row_major> bh, bl;
        wmma::load_matrix_sync(bh, Ah + (k*16)*72 + j*16, 72);
        wmma::load_matrix_sync(bl, Al + (k*16)*72 + j*16, 72);
        wmma::mma_sync(acc2[jj], ah, bh, acc2[jj]);
        wmma::mma_sync(acc2[jj], ah, bl, acc2[jj]);
        wmma::mma_sync(acc2[jj], al, bh, acc2[jj]);
      }
    }
    __syncthreads();
#pragma unroll
    for (int jj = 0; jj < 2; jj++)
      wmma::store_matrix_sync(outF + mg*68 + (j0+jj)*16, acc2[jj], 68, wmma::mem_row_major);
    __syncthreads();
    for (int idx = tid; idx < 4096; idx += 256)
      atomicAdd(&g_C[b*4096 + idx], outF[(idx>>6)*68 + (idx&63)]);
  } else {
    __syncthreads();
    float* O = g_V + ((size_t)b*TOK + n0)*CH_;
    float s = 0.f, ss = 0.f;
    for (int idx = tid; idx < 8192; idx += 256){
      float f = outF[(idx>>6)*68 + (idx&63)];
      O[idx] = f;
      float lf = leaky(f); s += lf; ss = fmaf(lf, lf, ss);
    }
    red[tid] = s; red[256 + tid] = ss;
    __syncthreads();
    if (tid < 64){
      atomicAdd(&g_stats[128 + tid],
                red[tid] + red[tid+64] + red[tid+128] + red[tid+192]);
      atomicAdd(&g_stats[192 + tid],
                red[256+tid] + red[320+tid] + red[384+tid] + red[448+tid]);
    }
  }
}

// ====== fused: attn-epilogue (sliding-window dwconv) + LN-FF — 512 threads ======
#define SM_F_BYTES 90112
template<int STATS>
__global__ __launch_bounds__(512,2)
void k_fused12(const float* __restrict__ wff, const float* __restrict__ bproj,
               const float* __restrict__ lng, const float* __restrict__ lnb,
               const float* __restrict__ wpos){
  extern __shared__ unsigned char smraw[];
  float* xs = (float*)smraw;
  __nv_bfloat16* Ah = (__nv_bfloat16*)(smraw + 34816);
  __nv_bfloat16* Al = (__nv_bfloat16*)(smraw + 53248);
  __nv_bfloat16* Bh = (__nv_bfloat16*)(smraw + 71680);
  __nv_bfloat16* Bl = (__nv_bfloat16*)(smraw + 80896);
  float* outF = (float*)(smraw + 34816);
  __shared__ float s_bias[64], s_g[64], s_bb[64];
  __shared__ float red[1024];
  __shared__ float wp[576];

  int tid = threadIdx.x, wid = tid >> 5;
  int b = blockIdx.x, n0 = blockIdx.y * 128;
  int y = blockIdx.y;
  int m0 = (wid & 7) * 16;      // m-strip
  int j0 = (wid >> 3) * 2;      // j-half: frags j0, j0+1

  if (tid < 64){ s_bias[tid] = bproj[tid]; s_g[tid] = lng[tid]; s_bb[tid] = lnb[tid]; }
  for (int i = tid; i < 576; i += 512) wp[i] = wpos[i];

  const float4* IN4 = (const float4*)(g_V + ((size_t)b*TOK + n0)*CH_);
  for (int i = tid; i < 2048; i += 512){
    float4 v = IN4[i];
    int t = i >> 4, c = (i & 15) * 4;
    __nv_bfloat16 h, l;
    split_bf16(v.x, h, l); Ah[t*72+c  ] = h; Al[t*72+c  ] = l;
    split_bf16(v.y, h, l); Ah[t*72+c+1] = h; Al[t*72+c+1] = l;
    split_bf16(v.z, h, l); Ah[t*72+c+2] = h; Al[t*72+c+2] = l;
    split_bf16(v.w, h, l); Ah[t*72+c+3] = h; Al[t*72+c+3] = l;
  }
  const float4* WE4 = (const float4*)(g_Weff + b*4096);
  for (int i = tid; i < 1024; i += 512){
    float4 v = WE4[i];
    int k = i >> 4, n = (i & 15) * 4;
    __nv_bfloat16 h, l;
    split_bf16(v.x, h, l); Bh[k*72+n  ] = h; Bl[k*72+n  ] = l;
    split_bf16(v.y, h, l); Bh[k*72+n+1] = h; Bl[k*72+n+1] = l;
    split_bf16(v.z, h, l); Bh[k*72+n+2] = h; Bl[k*72+n+2] = l;
    split_bf16(v.w, h, l); Bh[k*72+n+3] = h; Bl[k*72+n+3] = l;
  }
  __syncthreads();

  // MMA1: V @ Weff -> xs (each warp: 16 rows x 32 cols)
  {
    wmma::fragment<wmma::accumulator,16,16,16,float> acc[2];
#pragma unroll
    for (int j = 0; j < 2; j++) wmma::fill_fragment(acc[j], 0.f);
#pragma unroll
    for (int k = 0; k < 4; k++){
      wmma::fragment<wmma::matrix_a,16,16,16,__nv_bfloat16,wmma::row_major> ah, al;
      wmma::load_matrix_sync(ah, Ah + m0*72 + k*16, 72);
      wmma::load_matrix_sync(al, Al + m0*72 + k*16, 72);
#pragma unroll
      for (int jj = 0; jj < 2; jj++){
        int j = j0 + jj;
        wmma::fragment<wmma::matrix_b,16,16,16,__nv_bfloat16,wmma::row_major> bh, bl;
        wmma::load_matrix_sync(bh, Bh + (k*16)*72 + j*16, 72);
        wmma::load_matrix_sync(bl, Bl + (k*16)*72 + j*16, 72);
        wmma::mma_sync(acc[jj], ah, bh, acc[jj]);
        wmma::mma_sync(acc[jj], ah, bl, acc[jj]);
        wmma::mma_sync(acc[jj], al, bh, acc[jj]);
      }
    }
    __syncthreads();
#pragma unroll
    for (int jj = 0; jj < 2; jj++)
      wmma::store_matrix_sync(xs + m0*68 + (j0+jj)*16, acc[jj], 68, wmma::mem_row_major);
  }
  __syncthreads();

  // Y = XT + (xs + bias) * dwconv(V) -> xs ; restage wff -> Bh/Bl
  // sliding-window dwconv: thread handles 4 consecutive t for one c4
  {
    const float4* XT4 = (const float4*)(g_XT + ((size_t)b*TOK + n0)*CH_);
    const float* Vb = g_V + (size_t)b*TOK*CH_;
    int c4 = tid & 15, c = c4 * 4;
    int tseg = (tid >> 4) * 4;
    bool hasM = (y > 0), hasP = (y < 127);
    const float* rowM = Vb + ((size_t)(y - 1) * 128) * 64;
    const float* rowC = Vb + ((size_t)(y    ) * 128) * 64;
    const float* rowP = Vb + ((size_t)(y + 1) * 128) * 64;
    float4 vL[3], vC[3], vR[3];
    float4 z4 = make_float4(0.f, 0.f, 0.f, 0.f);
    #define LOADCOL(xx, dst) do { \
      int _x = (xx); \
      if (_x < 0 || _x > 127){ (dst)[0] = z4; (dst)[1] = z4; (dst)[2] = z4; } \
      else { \
        (dst)[0] = hasM ? *(const float4*)&rowM[_x*64 + c] : z4; \
        (dst)[1] = *(const float4*)&rowC[_x*64 + c]; \
        (dst)[2] = hasP ? *(const float4*)&rowP[_x*64 + c] : z4; \
      } \
    } while(0)
    LOADCOL(tseg - 1, vL);
    LOADCOL(tseg,     vC);
#pragma unroll
    for (int tt = 0; tt < 4; tt++){
      int t = tseg + tt;
      LOADCOL(t + 1, vR);
      float p0 = 0.f, p1 = 0.f, p2 = 0.f, p3 = 0.f;
#pragma unroll
      for (int r = 0; r < 3; r++){
        p0 = fmaf(vL[r].x, wp[(c  )*9 + r*3 + 0], p0);
        p1 = fmaf(vL[r].y, wp[(c+1)*9 + r*3 + 0], p1);
        p2 = fmaf(vL[r].z, wp[(c+2)*9 + r*3 + 0], p2);
        p3 = fmaf(vL[r].w, wp[(c+3)*9 + r*3 + 0], p3);
        p0 = fmaf(vC[r].x, wp[(c  )*9 + r*3 + 1], p0);
        p1 = fmaf(vC[r].y, wp[(c+1)*9 + r*3 + 1], p1);
        p2 = fmaf(vC[r].z, wp[(c+2)*9 + r*3 + 1], p2);
        p3 = fmaf(vC[r].w, wp[(c+3)*9 + r*3 + 1], p3);
        p0 = fmaf(vR[r].x, wp[(c  )*9 + r*3 + 2], p0);
        p1 = fmaf(vR[r].y, wp[(c+1)*9 + r*3 + 2], p1);
        p2 = fmaf(vR[r].z, wp[(c+2)*9 + r*3 + 2], p2);
        p3 = fmaf(vR[r].w, wp[(c+3)*9 + r*3 + 2], p3);
      }
      float4 xv = XT4[t*16 + c4];
      float* o = &xs[t*68 + c];
      o[0] = xv.x + (o[0] + s_bias[c  ]) * p0;
      o[1] = xv.y + (o[1] + s_bias[c+1]) * p1;
      o[2] = xv.z + (o[2] + s_bias[c+2]) * p2;
      o[3] = xv.w + (o[3] + s_bias[c+3]) * p3;
#pragma unroll
      for (int r = 0; r < 3; r++){ vL[r] = vC[r]; vC[r] = vR[r]; }
    }
    #undef LOADCOL
    const float4* WF4 = (const float4*)wff;
    for (int i = tid; i < 1024; i += 512){
      float4 v = WF4[i];
      int k = i >> 4, n = (i & 15) * 4;
      __nv_bfloat16 h, l;
      split_bf16(v.x, h, l); Bh[k*72+n  ] = h; Bl[k*72+n  ] = l;
      split_bf16(v.y, h, l); Bh[k*72+n+1] = h; Bl[k*72+n+1] = l;
      split_bf16(v.z, h, l); Bh[k*72+n+2] = h; Bl[k*72+n+2] = l;
      split_bf16(v.w, h, l); Bh[k*72+n+3] = h; Bl[k*72+n+3] = l;
    }
  }
  __syncthreads();

  // LN(Y) -> Ah/Al
  if (tid < 128){
    const float* row = &xs[tid*68];
    float s = 0.f, ss = 0.f;
#pragma unroll
    for (int c = 0; c < 64; c++){ float xv = row[c]; s += xv; ss = fmaf(xv, xv, ss); }
    float mean = s * (1.f/64.f);
    float rstd = rsqrtf(ss*(1.f/64.f) - mean*mean + 1e-5f);
#pragma unroll
    for (int c = 0; c < 64; c++){
      float f = (row[c] - mean) * rstd * s_g[c] + s_bb[c];
      __nv_bfloat16 h, l; split_bf16(f, h, l);
      Ah[tid*72 + c] = h; Al[tid*72 + c] = l;
    }
  }
  __syncthreads();

  // MMA2: LN(Y) @ wff -> outF
  {
    wmma::fragment<wmma::accumulator,16,16,16,float> acc[2];
#pragma unroll
    for (int j = 0; j < 2; j++) wmma::fill_fragment(acc[j], 0.f);
#pragma unroll
    for (int k = 0; k < 4; k++){
      wmma::fragment<wmma::matrix_a,16,16,16,__nv_bfloat16,wmma::row_major> ah, al;
      wmma::load_matrix_sync(ah, Ah + m0*72 + k*16, 72);
      wmma::load_matrix_sync(al, Al + m0*72 + k*16, 72);
#pragma unroll
      for (int jj = 0; jj < 2; jj++){
        int j = j0 + jj;
        wmma::fragment<wmma::matrix_b,16,16,16,__nv_bfloat16,wmma::row_major> bh, bl;
        wmma::load_matrix_sync(bh, Bh + (k*16)*72 + j*16, 72);
        wmma::load_matrix_sync(bl, Bl + (k*16)*72 + j*16, 72);
        wmma::mma_sync(acc[jj], ah, bh, acc[jj]);
        wmma::mma_sync(acc[jj], ah, bl, acc[jj]);
        wmma::mma_sync(acc[jj], al, bh, acc[jj]);
      }
    }
    __syncthreads();
#pragma unroll
    for (int jj = 0; jj < 2; jj++)
      wmma::store_matrix_sync(outF + m0*68 + (j0+jj)*16, acc[jj], 68, wmma::mem_row_major);
  }
  __syncthreads();

  float s = 0.f, ss = 0.f;
  if (STATS){
    float* XT = g_XT + ((size_t)b*TOK + n0)*CH_;
    for (int idx = tid; idx < 8192; idx += 512){
      float nv = xs[(idx>>6)*68 + (idx&63)] + outF[(idx>>6)*68 + (idx&63)];
      XT[idx] = nv;
      float lf = leaky(nv); s += lf; ss = fmaf(lf, lf, ss);
    }
    red[tid] = s; red[512 + tid] = ss;
    __syncthreads();
    if (tid < 64){
      float a = 0.f, a2 = 0.f;
#pragma unroll
      for (int k = 0; k < 8; k++){
        a  += red[tid + 64*k];
        a2 += red[512 + tid + 64*k];
      }
      atomicAdd(&g_stats[tid],      a);
      atomicAdd(&g_stats[64 + tid], a2);
    }
  } else {
    float4* XT4 = (float4*)(g_XT + ((size_t)b*TOK + n0)*CH_);
    for (int i = tid; i < 2048; i += 512){
      int t = i >> 4, c = (i & 15) * 4;
      float4 o;
      o.x = xs[t*68+c  ] + outF[t*68+c  ];
      o.y = xs[t*68+c+1] + outF[t*68+c+1];
      o.z = xs[t*68+c+2] + outF[t*68+c+2];
      o.w = xs[t*68+c+3] + outF[t*68+c+3];
      XT4[i] = o;
    }
  }
}

// ------- per-batch attention stats + fold into Weff -------
__global__ void k_attn_weff(const float* __restrict__ wq, const float* __restrict__ wk,
                            const float* __restrict__ wproj){
  extern __shared__ float sm[];
  float* Cs  = sm;
  float* wqs = sm + 4096;
  float* wks = sm + 8192;
  float* wps = sm + 12288;
  float* T1  = sm + 16384;
  float* T2  = sm + 20480;
  __shared__ float attn_s[512];
  __shared__ float qq[64], kk[64];
  int b = blockIdx.x;
  for (int i = threadIdx.x; i < 4096; i += 256){
    Cs[i]  = g_C[b*4096 + i];
    wqs[i] = wq[i]; wks[i] = wk[i]; wps[i] = wproj[i];
  }
  __syncthreads();
  for (int i = threadIdx.x; i < 4096; i += 256){
    int r = i >> 6, e = i & 63; float s1 = 0.f, s2 = 0.f;
    for (int c = 0; c < 64; c++){
      float cv = Cs[r*64 + c];
      s1 = fmaf(cv, wqs[c*64 + e], s1);
      s2 = fmaf(cv, wks[c*64 + e], s2);
    }
    T1[i] = s1; T2[i] = s2;
  }
  __syncthreads();
  if (threadIdx.x < 64){
    int e = threadIdx.x; float s1 = 0.f, s2 = 0.f;
    for (int c = 0; c < 64; c++){
      s1 = fmaf(wqs[c*64 + e], T1[c*64 + e], s1);
      s2 = fmaf(wks[c*64 + e], T2[c*64 + e], s2);
    }
    qq[e] = s1; kk[e] = s2;
  }
  __syncthreads();
  if (threadIdx.x < 64){
    int h = threadIdx.x >> 3, dd = threadIdx.x & 7;
    float nk = fmaxf(sqrtf(kk[h*8 + dd]), 1e-12f);
    float lo[8]; float mx = -3.4e38f;
#pragma unroll
    for (int e = 0; e < 8; e++){
      float gg = 0.f;
      for (int c = 0; c < 64; c++)
        gg = fmaf(wks[c*64 + h*8 + dd], T1[c*64 + h*8 + e], gg);
      float nq = fmaxf(sqrtf(qq[h*8 + e]), 1e-12f);
      lo[e] = gg / (nk * nq);
      mx = fmaxf(mx, lo[e]);
    }
    float sum = 0.f;
#pragma unroll
    for (int e = 0; e < 8; e++){ lo[e] = expf(lo[e] - mx); sum += lo[e]; }
    float inv = 1.f / sum;
#pragma unroll
    for (int e = 0; e < 8; e++) attn_s[(h*8 + dd)*8 + e] = lo[e] * inv;
  }
  __syncthreads();
  for (int i = threadIdx.x; i < 4096; i += 256){
    int cin = i >> 6, oc = i & 63;
    int h = cin >> 3, e = cin & 7;
    float s = 0.f;
#pragma unroll
    for (int dd = 0; dd < 8; dd++)
      s = fmaf(attn_s[(h*8 + dd)*8 + e], wps[(h*8 + dd)*64 + oc], s);
    g_Weff[b*4096 + i] = s;
  }
}

// ---- BN2 + residual + NCHW out + pooled sums ----
__global__ void k_bn2_add_pool(const float* __restrict__ x_orig, float* __restrict__ out,
                               const float* __restrict__ g2, const float* __restrict__ b2){
  int b = blockIdx.x, n0 = blockIdx.y * 64;
  __shared__ float s[64*65];
  __shared__ float scale[64], shift[64];
  if (threadIdx.x < 64){
    int c = threadIdx.x;
    float m   = g_stats[128 + c] * (1.f/CNT);
    float var = g_stats[192 + c] * (1.f/CNT) - m*m;
    float sc  = g2[c] * rsqrtf(var + 1e-4f);
    scale[c] = sc; shift[c] = b2[c] - m*sc;
  }
  const float* R = g_V + ((size_t)b*TOK + n0)*CH_;
  for (int idx = threadIdx.x; idx < 4096; idx += 256){
    int t = idx >> 6, c = idx & 63;
    s[t*65 + c] = R[idx];
  }
  __syncthreads();
  int y = n0 >> 7, x0 = n0 & 127;
  int iblk = y >> 4, jbase = x0 >> 4;
  const float* xb = x_orig + (size_t)b*CH_*TOK;
  float* ob = out + (size_t)b*CH_*TOK;
  for (int idx = threadIdx.x; idx < 4096; idx += 256){
    int c = idx >> 6, j = idx & 63;
    float f = leaky(s[j*65 + c]) * scale[c] + shift[c];
    size_t off = (size_t)c*TOK + n0 + j;
    float sval = f + xb[off];
    ob[off] = sval;
    float r = sval;
    r += __shfl_down_sync(0xffffffffu, r, 8, 16);
    r += __shfl_down_sync(0xffffffffu, r, 4, 16);
    r += __shfl_down_sync(0xffffffffu, r, 2, 16);
    r += __shfl_down_sync(0xffffffffu, r, 1, 16);
    if ((threadIdx.x & 15) == 0)
      atomicAdd(&g_pooled[(b*64 + c)*64 + iblk*8 + jbase + (j >> 4)], r);
  }
}

__global__ void k_minmax(){
  float mn = 3.4e38f, mx = -3.4e38f;
  for (int i = threadIdx.x; i < B_*4096; i += 1024){
    float v = g_pooled[i] * (1.f/256.f);
    mn = fminf(mn, v); mx = fmaxf(mx, v);
  }
#pragma unroll
  for (int o = 16; o > 0; o >>= 1){
    mn = fminf(mn, __shfl_xor_sync(0xffffffffu, mn, o));
    mx = fmaxf(mx, __shfl_xor_sync(0xffffffffu, mx, o));
  }
  __shared__ float smn[32], smx[32];
  if ((threadIdx.x & 31) == 0){ smn[threadIdx.x >> 5] = mn; smx[threadIdx.x >> 5] = mx; }
  __syncthreads();
  if (threadIdx.x < 32){
    mn = smn[threadIdx.x]; mx = smx[threadIdx.x];
#pragma unroll
    for (int o = 16; o > 0; o >>= 1){
      mn = fminf(mn, __shfl_xor_sync(0xffffffffu, mn, o));
      mx = fmaxf(mx, __shfl_xor_sync(0xffffffffu, mx, o));
    }
    if (threadIdx.x == 0){ g_minmax[0] = mn; g_minmax[1] = mx; }
  }
}

__global__ void k_gate(const float* __restrict__ w1, const float* __restrict__ w2){
  int b = blockIdx.x;
  __shared__ float y[4096];
  __shared__ float S[64];
  __shared__ float g0[64];
  __shared__ float hid[4];
  float mn = g_minmax[0];
  float inv = 1.f / (g_minmax[1] - mn);
  for (int i = threadIdx.x; i < 4096; i += 64)
    y[i] = (g_pooled[b*4096 + i] * (1.f/256.f) - mn) * inv;
  __syncthreads();
  {
    int i = threadIdx.x; float s = 0.f;
    for (int c = 0; c < 64; c++) s += y[c*64 + i];
    S[i] = s;
  }
  __syncthreads();
  {
    int c = threadIdx.x; float s = 0.f, sm2 = 0.f;
    for (int i = 0; i < 64; i++){
      s = fmaf(y[c*64 + i], S[i], s);
      sm2 += g_pooled[b*4096 + c*64 + i];
    }
    g0[c] = (s * (1.f/64.f)) * (sm2 * (1.f/16384.f));
  }
  __syncthreads();
  if (threadIdx.x < 4){
    int j = threadIdx.x; float h = 0.f;
    for (int c = 0; c < 64; c++) h = fmaf(g0[c], w1[c*4 + j], h);
    hid[j] = leaky(h);
  }
  __syncthreads();
  {
    int c = threadIdx.x; float o = 0.f;
#pragma unroll
    for (int j = 0; j < 4; j++) o = fmaf(hid[j], w2[j*64 + c], o);
    g_gate[b*64 + c] = 1.f / (1.f + expf(-o));
  }
}

__global__ void k_scale(float* __restrict__ out){
  size_t i = (size_t)blockIdx.x * 256 + threadIdx.x;
  out[i] *= g_gate[i >> 14];
}

// ================================ launch ========================================
extern "C" void kernel_launch(void* const* d_in, const int* in_sizes, int n_in,
                              void* d_out, int out_size){
  const float* x     = (const float*)d_in[0];
  const float* wq    = (const float*)d_in[1];
  const float* wk    = (const float*)d_in[2];
  const float* wv    = (const float*)d_in[3];
  const float* wproj = (const float*)d_in[4];
  const float* bproj = (const float*)d_in[5];
  const float* wpos  = (const float*)d_in[6];
  const float* ln_g  = (const float*)d_in[7];
  const float* ln_b  = (const float*)d_in[8];
  const float* wff   = (const float*)d_in[9];
  const float* bn1_g = (const float*)d_in[10];
  const float* bn1_b = (const float*)d_in[11];
  const float* wd    = (const float*)d_in[12];
  const float* bn2_g = (const float*)d_in[13];
  const float* bn2_b = (const float*)d_in[14];
  const float* sw1   = (const float*)d_in[15];
  const float* sw2   = (const float*)d_in[16];
  float* out = (float*)d_out;

  cudaFuncSetAttribute(k_gemm<0>,    cudaFuncAttributeMaxDynamicSharedMemorySize, SM_GEMM_BYTES);
  cudaFuncSetAttribute(k_gemm<3>,    cudaFuncAttributeMaxDynamicSharedMemorySize, SM_GEMM_BYTES);
  cudaFuncSetAttribute(k_fused12<0>, cudaFuncAttributeMaxDynamicSharedMemorySize, SM_F_BYTES);
  cudaFuncSetAttribute(k_fused12<1>, cudaFuncAttributeMaxDynamicSharedMemorySize, SM_F_BYTES);
  cudaFuncSetAttribute(k_attn_weff,  cudaFuncAttributeMaxDynamicSharedMemorySize, 100*1024);

  void *pC = nullptr, *pStats = nullptr, *pPooled = nullptr;
  cudaGetSymbolAddress(&pC, g_C);
  cudaGetSymbolAddress(&pStats, g_stats);
  cudaGetSymbolAddress(&pPooled, g_pooled);

  cudaMemsetAsync(pStats, 0, 256*sizeof(float));
  k_transpose_in<<<dim3(16, 256), 256>>>(x);
  for (int l = 0; l < 2; l++){
    cudaMemsetAsync(pC, 0, 16*4096*sizeof(float));
    k_gemm<0><<<dim3(16, 128), 256, SM_GEMM_BYTES>>>(wv + l*4096, nullptr, nullptr);
    k_attn_weff<<<16, 256, 6*4096*sizeof(float)>>>(wq + l*4096, wk + l*4096, wproj + l*4096);
    if (l == 0)
      k_fused12<0><<<dim3(16, 128), 512, SM_F_BYTES>>>(wff + l*4096, bproj + l*64, ln_g + l*64, ln_b + l*64, wpos + l*576);
    else
      k_fused12<1><<<dim3(16, 128), 512, SM_F_BYTES>>>(wff + l*4096, bproj + l*64, ln_g + l*64, ln_b + l*64, wpos + l*576);
  }
  k_gemm<3><<<dim3(16, 128), 256, SM_GEMM_BYTES>>>(wd, bn1_g, bn1_b);
  cudaMemsetAsync(pPooled, 0, 16*4096*sizeof(float));
  k_bn2_add_pool<<<dim3(16, 256), 256>>>(x, out, bn2_g, bn2_b);
  k_minmax<<<1, 1024>>>();
  k_gate<<<16, 64>>>(sw1, sw2);
  k_scale<<<65536, 256>>>(out);
}

// round 16
// speedup vs baseline: 1.2142x; 1.2142x over previous
#include <cuda_runtime.h>
#include <cuda_bf16.h>
#include <mma.h>
#include <cstdint>

using namespace nvcuda;

#define B_   16
#define CH_  64
#define TOK  16384
#define CNT  (16.0f*16384.0f)

__device__ float g_XT[B_*TOK*CH_];
__device__ float g_V [B_*TOK*CH_];
__device__ float g_C    [B_*64*64];
__device__ float g_Weff [B_*64*64];
__device__ float g_stats[256];
__device__ float g_pooled[B_*64*64];
__device__ float g_minmax[2];
__device__ float g_gate[B_*64];

__device__ __forceinline__ float leaky(float x){ return x >= 0.f ? x : 0.2f*x; }
__device__ __forceinline__ void split_bf16(float f, __nv_bfloat16& h, __nv_bfloat16& l){
  h = __float2bfloat16_rn(f);
  l = __float2bfloat16_rn(f - __bfloat162float(h));
}

// ---------------- NCHW -> BHWC transpose (float4 both sides) ----------------
__global__ void k_transpose_in(const float* __restrict__ x){
  int b = blockIdx.x, n0 = blockIdx.y * 64;
  __shared__ float s[64*65];
  const float* xb = x + (size_t)b*CH_*TOK;
  for (int i = threadIdx.x; i < 1024; i += 256){
    int c = i >> 4, j4 = (i & 15) * 4;
    float4 v = *(const float4*)&xb[(size_t)c*TOK + n0 + j4];
    s[c*65 + j4  ] = v.x;
    s[c*65 + j4+1] = v.y;
    s[c*65 + j4+2] = v.z;
    s[c*65 + j4+3] = v.w;
  }
  __syncthreads();
  float* xt = g_XT + ((size_t)b*TOK + n0)*CH_;
  for (int i = threadIdx.x; i < 1024; i += 256){
    int j = i >> 4, c4 = (i & 15) * 4;
    float4 v;
    v.x = s[(c4  )*65 + j];
    v.y = s[(c4+1)*65 + j];
    v.z = s[(c4+2)*65 + j];
    v.w = s[(c4+3)*65 + j];
    *(float4*)&xt[j*CH_ + c4] = v;
  }
}

// =============== wmma GEMM — slim smem (R14 verbatim) ===============
// MODE 0: V = XT @ W (direct global store) + FUSED gram partial
// MODE 3: V = BN1(leaky(XT)) @ W ; leaky stats -> g_stats[128..255]
#define SM_GEMM_BYTES 55296
template<int MODE>
__global__ __launch_bounds__(256)
void k_gemm(const float* __restrict__ W, const float* __restrict__ aux0,
            const float* __restrict__ aux1){
  extern __shared__ unsigned char smraw[];
  __nv_bfloat16* Ah = (__nv_bfloat16*)smraw;
  __nv_bfloat16* Al = (__nv_bfloat16*)(smraw + 18432);
  __nv_bfloat16* Bh = (__nv_bfloat16*)(smraw + 36864);
  __nv_bfloat16* Bl = (__nv_bfloat16*)(smraw + 46080);
  float* outF = (float*)smraw;
  __shared__ float s_a[64], s_b[64];
  __shared__ float red[512];

  int tid = threadIdx.x, wid = tid >> 5;
  int b = blockIdx.x, n0 = blockIdx.y * 128;
  int m0 = wid * 16;

  if (MODE == 3 && tid < 64){
    float m   = g_stats[tid]      * (1.f/CNT);
    float var = g_stats[64 + tid] * (1.f/CNT) - m*m;
    float sc  = aux0[tid] * rsqrtf(var + 1e-4f);
    s_a[tid] = sc; s_b[tid] = aux1[tid] - m*sc;
  }

  const float4* W4 = (const float4*)W;
  for (int i = tid; i < 1024; i += 256){
    float4 v = W4[i];
    int k = i >> 4, n = (i & 15) * 4;
    __nv_bfloat16 h, l;
    split_bf16(v.x, h, l); Bh[k*72+n  ] = h; Bl[k*72+n  ] = l;
    split_bf16(v.y, h, l); Bh[k*72+n+1] = h; Bl[k*72+n+1] = l;
    split_bf16(v.z, h, l); Bh[k*72+n+2] = h; Bl[k*72+n+2] = l;
    split_bf16(v.w, h, l); Bh[k*72+n+3] = h; Bl[k*72+n+3] = l;
  }
  __syncthreads();

  const float4* IN4 = (const float4*)(g_XT + ((size_t)b*TOK + n0)*CH_);
  for (int i = tid; i < 2048; i += 256){
    float4 v = IN4[i];
    int t = i >> 4, c = (i & 15) * 4;
    float f0 = v.x, f1 = v.y, f2 = v.z, f3 = v.w;
    if (MODE == 3){
      f0 = leaky(f0)*s_a[c  ] + s_b[c  ];
      f1 = leaky(f1)*s_a[c+1] + s_b[c+1];
      f2 = leaky(f2)*s_a[c+2] + s_b[c+2];
      f3 = leaky(f3)*s_a[c+3] + s_b[c+3];
    }
    __nv_bfloat16 h, l;
    split_bf16(f0, h, l); Ah[t*72+c  ] = h; Al[t*72+c  ] = l;
    split_bf16(f1, h, l); Ah[t*72+c+1] = h; Al[t*72+c+1] = l;
    split_bf16(f2, h, l); Ah[t*72+c+2] = h; Al[t*72+c+2] = l;
    split_bf16(f3, h, l); Ah[t*72+c+3] = h; Al[t*72+c+3] = l;
  }
  __syncthreads();

  {
    wmma::fragment<wmma::accumulator,16,16,16,float> acc[4];
#pragma unroll
    for (int j = 0; j < 4; j++) wmma::fill_fragment(acc[j], 0.f);
#pragma unroll
    for (int k = 0; k < 4; k++){
      wmma::fragment<wmma::matrix_a,16,16,16,__nv_bfloat16,wmma::row_major> ah, al;
      wmma::load_matrix_sync(ah, Ah + m0*72 + k*16, 72);
      wmma::load_matrix_sync(al, Al + m0*72 + k*16, 72);
#pragma unroll
      for (int j = 0; j < 4; j++){
        wmma::fragment<wmma::matrix_b,16,16,16,__nv_bfloat16,wmma::row_major> bh, bl;
        wmma::load_matrix_sync(bh, Bh + (k*16)*72 + j*16, 72);
        wmma::load_matrix_sync(bl, Bl + (k*16)*72 + j*16, 72);
        wmma::mma_sync(acc[j], ah, bh, acc[j]);
        wmma::mma_sync(acc[j], ah, bl, acc[j]);
        wmma::mma_sync(acc[j], al, bh, acc[j]);
      }
    }
    if (MODE == 0){
      float* O = g_V + ((size_t)b*TOK + n0 + m0)*CH_;
#pragma unroll
      for (int j = 0; j < 4; j++)
        wmma::store_matrix_sync(O + j*16, acc[j], 64, wmma::mem_row_major);
    } else {
      __syncthreads();
#pragma unroll
      for (int j = 0; j < 4; j++)
        wmma::store_matrix_sync(outF + m0*68 + j*16, acc[j], 68, wmma::mem_row_major);
    }
  }

  if (MODE == 0){
    int mwid = wid & 3, nh = wid >> 2;
    int mg = mwid * 16, j0 = nh * 2;
    wmma::fragment<wmma::accumulator,16,16,16,float> acc2[2];
#pragma unroll
    for (int j = 0; j < 2; j++) wmma::fill_fragment(acc2[j], 0.f);
#pragma unroll
    for (int k = 0; k < 8; k++){
      wmma::fragment<wmma::matrix_a,16,16,16,__nv_bfloat16,wmma::col_major> ah, al;
      wmma::load_matrix_sync(ah, Ah + (k*16)*72 + mg, 72);
      wmma::load_matrix_sync(al, Al + (k*16)*72 + mg, 72);
#pragma unroll
      for (int jj = 0; jj < 2; jj++){
        int j = j0 + jj;
        wmma::fragment<wmma::matrix_b,16,16,16,__nv_bfloat16,wmma::row_major> bh, bl;
        wmma::load_matrix_sync(bh, Ah + (k*16)*72 + j*16, 72);
        wmma::load_matrix_sync(bl, Al + (k*16)*72 + j*16, 72);
        wmma::mma_sync(acc2[jj], ah, bh, acc2[jj]);
        wmma::mma_sync(acc2[jj], ah, bl, acc2[jj]);
        wmma::mma_sync(acc2[jj], al, bh, acc2[jj]);
      }
    }
    __syncthreads();
#pragma unroll
    for (int jj = 0; jj < 2; jj++)
      wmma::store_matrix_sync(outF + mg*68 + (j0+jj)*16, acc2[jj], 68, wmma::mem_row_major);
    __syncthreads();
    for (int idx = tid; idx < 4096; idx += 256)
      atomicAdd(&g_C[b*4096 + idx], outF[(idx>>6)*68 + (idx&63)]);
  } else {
    __syncthreads();
    float* O = g_V + ((size_t)b*TOK + n0)*CH_;
    float s = 0.f, ss = 0.f;
    for (int idx = tid; idx < 8192; idx += 256){
      float f = outF[(idx>>6)*68 + (idx&63)];
      O[idx] = f;
      float lf = leaky(f); s += lf; ss = fmaf(lf, lf, ss);
    }
    red[tid] = s; red[256 + tid] = ss;
    __syncthreads();
    if (tid < 64){
      atomicAdd(&g_stats[128 + tid],
                red[tid] + red[tid+64] + red[tid+128] + red[tid+192]);
      atomicAdd(&g_stats[192 + tid],
                red[256+tid] + red[320+tid] + red[384+tid] + red[448+tid]);
    }
  }
}

// ====== fused: attn-epilogue (sliding-window dwconv) + LN-FF (R14 verbatim, 256 thr) ======
#define SM_F_BYTES 90112
template<int STATS>
__global__ __launch_bounds__(256,2)
void k_fused12(const float* __restrict__ wff, const float* __restrict__ bproj,
               const float* __restrict__ lng, const float* __restrict__ lnb,
               const float* __restrict__ wpos){
  extern __shared__ unsigned char smraw[];
  float* xs = (float*)smraw;
  __nv_bfloat16* Ah = (__nv_bfloat16*)(smraw + 34816);
  __nv_bfloat16* Al = (__nv_bfloat16*)(smraw + 53248);
  __nv_bfloat16* Bh = (__nv_bfloat16*)(smraw + 71680);
  __nv_bfloat16* Bl = (__nv_bfloat16*)(smraw + 80896);
  float* outF = (float*)(smraw + 34816);
  __shared__ float s_bias[64], s_g[64], s_bb[64];
  __shared__ float red[512];
  __shared__ float wp[576];

  int tid = threadIdx.x, wid = tid >> 5;
  int b = blockIdx.x, n0 = blockIdx.y * 128;
  int y = blockIdx.y;
  int m0 = wid * 16;

  if (tid < 64){ s_bias[tid] = bproj[tid]; s_g[tid] = lng[tid]; s_bb[tid] = lnb[tid]; }
  for (int i = tid; i < 576; i += 256) wp[i] = wpos[i];

  const float4* IN4 = (const float4*)(g_V + ((size_t)b*TOK + n0)*CH_);
  for (int i = tid; i < 2048; i += 256){
    float4 v = IN4[i];
    int t = i >> 4, c = (i & 15) * 4;
    __nv_bfloat16 h, l;
    split_bf16(v.x, h, l); Ah[t*72+c  ] = h; Al[t*72+c  ] = l;
    split_bf16(v.y, h, l); Ah[t*72+c+1] = h; Al[t*72+c+1] = l;
    split_bf16(v.z, h, l); Ah[t*72+c+2] = h; Al[t*72+c+2] = l;
    split_bf16(v.w, h, l); Ah[t*72+c+3] = h; Al[t*72+c+3] = l;
  }
  const float4* WE4 = (const float4*)(g_Weff + b*4096);
  for (int i = tid; i < 1024; i += 256){
    float4 v = WE4[i];
    int k = i >> 4, n = (i & 15) * 4;
    __nv_bfloat16 h, l;
    split_bf16(v.x, h, l); Bh[k*72+n  ] = h; Bl[k*72+n  ] = l;
    split_bf16(v.y, h, l); Bh[k*72+n+1] = h; Bl[k*72+n+1] = l;
    split_bf16(v.z, h, l); Bh[k*72+n+2] = h; Bl[k*72+n+2] = l;
    split_bf16(v.w, h, l); Bh[k*72+n+3] = h; Bl[k*72+n+3] = l;
  }
  __syncthreads();

  // MMA1: V @ Weff -> xs
  {
    wmma::fragment<wmma::accumulator,16,16,16,float> acc[4];
#pragma unroll
    for (int j = 0; j < 4; j++) wmma::fill_fragment(acc[j], 0.f);
#pragma unroll
    for (int k = 0; k < 4; k++){
      wmma::fragment<wmma::matrix_a,16,16,16,__nv_bfloat16,wmma::row_major> ah, al;
      wmma::load_matrix_sync(ah, Ah + m0*72 + k*16, 72);
      wmma::load_matrix_sync(al, Al + m0*72 + k*16, 72);
#pragma unroll
      for (int j = 0; j < 4; j++){
        wmma::fragment<wmma::matrix_b,16,16,16,__nv_bfloat16,wmma::row_major> bh, bl;
        wmma::load_matrix_sync(bh, Bh + (k*16)*72 + j*16, 72);
        wmma::load_matrix_sync(bl, Bl + (k*16)*72 + j*16, 72);
        wmma::mma_sync(acc[j], ah, bh, acc[j]);
        wmma::mma_sync(acc[j], ah, bl, acc[j]);
        wmma::mma_sync(acc[j], al, bh, acc[j]);
      }
    }
    __syncthreads();
#pragma unroll
    for (int j = 0; j < 4; j++)
      wmma::store_matrix_sync(xs + m0*68 + j*16, acc[j], 68, wmma::mem_row_major);
  }
  __syncthreads();

  // Y = XT + (xs + bias) * dwconv(V) -> xs ; restage wff -> Bh/Bl
  {
    const float4* XT4 = (const float4*)(g_XT + ((size_t)b*TOK + n0)*CH_);
    const float* Vb = g_V + (size_t)b*TOK*CH_;
    int c4 = tid & 15, c = c4 * 4;
    int tseg = (tid >> 4) * 8;
    bool hasM = (y > 0), hasP = (y < 127);
    const float* rowM = Vb + ((size_t)(y - 1) * 128) * 64;
    const float* rowC = Vb + ((size_t)(y    ) * 128) * 64;
    const float* rowP = Vb + ((size_t)(y + 1) * 128) * 64;
    float4 vL[3], vC[3], vR[3];
    float4 z4 = make_float4(0.f, 0.f, 0.f, 0.f);
    #define LOADCOL(xx, dst) do { \
      int _x = (xx); \
      if (_x < 0 || _x > 127){ (dst)[0] = z4; (dst)[1] = z4; (dst)[2] = z4; } \
      else { \
        (dst)[0] = hasM ? *(const float4*)&rowM[_x*64 + c] : z4; \
        (dst)[1] = *(const float4*)&rowC[_x*64 + c]; \
        (dst)[2] = hasP ? *(const float4*)&rowP[_x*64 + c] : z4; \
      } \
    } while(0)
    LOADCOL(tseg - 1, vL);
    LOADCOL(tseg,     vC);
#pragma unroll
    for (int tt = 0; tt < 8; tt++){
      int t = tseg + tt;
      LOADCOL(t + 1, vR);
      float p0 = 0.f, p1 = 0.f, p2 = 0.f, p3 = 0.f;
#pragma unroll
      for (int r = 0; r < 3; r++){
        p0 = fmaf(vL[r].x, wp[(c  )*9 + r*3 + 0], p0);
        p1 = fmaf(vL[r].y, wp[(c+1)*9 + r*3 + 0], p1);
        p2 = fmaf(vL[r].z, wp[(c+2)*9 + r*3 + 0], p2);
        p3 = fmaf(vL[r].w, wp[(c+3)*9 + r*3 + 0], p3);
        p0 = fmaf(vC[r].x, wp[(c  )*9 + r*3 + 1], p0);
        p1 = fmaf(vC[r].y, wp[(c+1)*9 + r*3 + 1], p1);
        p2 = fmaf(vC[r].z, wp[(c+2)*9 + r*3 + 1], p2);
        p3 = fmaf(vC[r].w, wp[(c+3)*9 + r*3 + 1], p3);
        p0 = fmaf(vR[r].x, wp[(c  )*9 + r*3 + 2], p0);
        p1 = fmaf(vR[r].y, wp[(c+1)*9 + r*3 + 2], p1);
        p2 = fmaf(vR[r].z, wp[(c+2)*9 + r*3 + 2], p2);
        p3 = fmaf(vR[r].w, wp[(c+3)*9 + r*3 + 2], p3);
      }
      float4 xv = XT4[t*16 + c4];
      float* o = &xs[t*68 + c];
      o[0] = xv.x + (o[0] + s_bias[c  ]) * p0;
      o[1] = xv.y + (o[1] + s_bias[c+1]) * p1;
      o[2] = xv.z + (o[2] + s_bias[c+2]) * p2;
      o[3] = xv.w + (o[3] + s_bias[c+3]) * p3;
#pragma unroll
      for (int r = 0; r < 3; r++){ vL[r] = vC[r]; vC[r] = vR[r]; }
    }
    #undef LOADCOL
    const float4* WF4 = (const float4*)wff;
    for (int i = tid; i < 1024; i += 256){
      float4 v = WF4[i];
      int k = i >> 4, n = (i & 15) * 4;
      __nv_bfloat16 h, l;
      split_bf16(v.x, h, l); Bh[k*72+n  ] = h; Bl[k*72+n  ] = l;
      split_bf16(v.y, h, l); Bh[k*72+n+1] = h; Bl[k*72+n+1] = l;
      split_bf16(v.z, h, l); Bh[k*72+n+2] = h; Bl[k*72+n+2] = l;
      split_bf16(v.w, h, l); Bh[k*72+n+3] = h; Bl[k*72+n+3] = l;
    }
  }
  __syncthreads();

  // LN(Y) -> Ah/Al
  if (tid < 128){
    const float* row = &xs[tid*68];
    float s = 0.f, ss = 0.f;
#pragma unroll
    for (int c = 0; c < 64; c++){ float xv = row[c]; s += xv; ss = fmaf(xv, xv, ss); }
    float mean = s * (1.f/64.f);
    float rstd = rsqrtf(ss*(1.f/64.f) - mean*mean + 1e-5f);
#pragma unroll
    for (int c = 0; c < 64; c++){
      float f = (row[c] - mean) * rstd * s_g[c] + s_bb[c];
      __nv_bfloat16 h, l; split_bf16(f, h, l);
      Ah[tid*72 + c] = h; Al[tid*72 + c] = l;
    }
  }
  __syncthreads();

  // MMA2: LN(Y) @ wff -> outF
  {
    wmma::fragment<wmma::accumulator,16,16,16,float> acc[4];
#pragma unroll
    for (int j = 0; j < 4; j++) wmma::fill_fragment(acc[j], 0.f);
#pragma unroll
    for (int k = 0; k < 4; k++){
      wmma::fragment<wmma::matrix_a,16,16,16,__nv_bfloat16,wmma::row_major> ah, al;
      wmma::load_matrix_sync(ah, Ah + m0*72 + k*16, 72);
      wmma::load_matrix_sync(al, Al + m0*72 + k*16, 72);
#pragma unroll
      for (int j = 0; j < 4; j++){
        wmma::fragment<wmma::matrix_b,16,16,16,__nv_bfloat16,wmma::row_major> bh, bl;
        wmma::load_matrix_sync(bh, Bh + (k*16)*72 + j*16, 72);
        wmma::load_matrix_sync(bl, Bl + (k*16)*72 + j*16, 72);
        wmma::mma_sync(acc[j], ah, bh, acc[j]);
        wmma::mma_sync(acc[j], ah, bl, acc[j]);
        wmma::mma_sync(acc[j], al, bh, acc[j]);
      }
    }
    __syncthreads();
#pragma unroll
    for (int j = 0; j < 4; j++)
      wmma::store_matrix_sync(outF + m0*68 + j*16, acc[j], 68, wmma::mem_row_major);
  }
  __syncthreads();

  float s = 0.f, ss = 0.f;
  if (STATS){
    float* XT = g_XT + ((size_t)b*TOK + n0)*CH_;
    for (int idx = tid; idx < 8192; idx += 256){
      float nv = xs[(idx>>6)*68 + (idx&63)] + outF[(idx>>6)*68 + (idx&63)];
      XT[idx] = nv;
      float lf = leaky(nv); s += lf; ss = fmaf(lf, lf, ss);
    }
    red[tid] = s; red[256 + tid] = ss;
    __syncthreads();
    if (tid < 64){
      atomicAdd(&g_stats[tid],
                red[tid] + red[tid+64] + red[tid+128] + red[tid+192]);
      atomicAdd(&g_stats[64 + tid],
                red[256+tid] + red[320+tid] + red[384+tid] + red[448+tid]);
    }
  } else {
    float4* XT4 = (float4*)(g_XT + ((size_t)b*TOK + n0)*CH_);
    for (int i = tid; i < 2048; i += 256){
      int t = i >> 4, c = (i & 15) * 4;
      float4 o;
      o.x = xs[t*68+c  ] + outF[t*68+c  ];
      o.y = xs[t*68+c+1] + outF[t*68+c+1];
      o.z = xs[t*68+c+2] + outF[t*68+c+2];
      o.w = xs[t*68+c+3] + outF[t*68+c+3];
      XT4[i] = o;
    }
  }
}

// ------- per-batch attention stats + fold into Weff -------
__global__ void k_attn_weff(const float* __restrict__ wq, const float* __restrict__ wk,
                            const float* __restrict__ wproj){
  extern __shared__ float sm[];
  float* Cs  = sm;
  float* wqs = sm + 4096;
  float* wks = sm + 8192;
  float* wps = sm + 12288;
  float* T1  = sm + 16384;
  float* T2  = sm + 20480;
  __shared__ float attn_s[512];
  __shared__ float qq[64], kk[64];
  int b = blockIdx.x;
  for (int i = threadIdx.x; i < 4096; i += 256){
    Cs[i]  = g_C[b*4096 + i];
    wqs[i] = wq[i]; wks[i] = wk[i]; wps[i] = wproj[i];
  }
  __syncthreads();
  for (int i = threadIdx.x; i < 4096; i += 256){
    int r = i >> 6, e = i & 63; float s1 = 0.f, s2 = 0.f;
    for (int c = 0; c < 64; c++){
      float cv = Cs[r*64 + c];
      s1 = fmaf(cv, wqs[c*64 + e], s1);
      s2 = fmaf(cv, wks[c*64 + e], s2);
    }
    T1[i] = s1; T2[i] = s2;
  }
  __syncthreads();
  if (threadIdx.x < 64){
    int e = threadIdx.x; float s1 = 0.f, s2 = 0.f;
    for (int c = 0; c < 64; c++){
      s1 = fmaf(wqs[c*64 + e], T1[c*64 + e], s1);
      s2 = fmaf(wks[c*64 + e], T2[c*64 + e], s2);
    }
    qq[e] = s1; kk[e] = s2;
  }
  __syncthreads();
  if (threadIdx.x < 64){
    int h = threadIdx.x >> 3, dd = threadIdx.x & 7;
    float nk = fmaxf(sqrtf(kk[h*8 + dd]), 1e-12f);
    float lo[8]; float mx = -3.4e38f;
#pragma unroll
    for (int e = 0; e < 8; e++){
      float gg = 0.f;
      for (int c = 0; c < 64; c++)
        gg = fmaf(wks[c*64 + h*8 + dd], T1[c*64 + h*8 + e], gg);
      float nq = fmaxf(sqrtf(qq[h*8 + e]), 1e-12f);
      lo[e] = gg / (nk * nq);
      mx = fmaxf(mx, lo[e]);
    }
    float sum = 0.f;
#pragma unroll
    for (int e = 0; e < 8; e++){ lo[e] = expf(lo[e] - mx); sum += lo[e]; }
    float inv = 1.f / sum;
#pragma unroll
    for (int e = 0; e < 8; e++) attn_s[(h*8 + dd)*8 + e] = lo[e] * inv;
  }
  __syncthreads();
  for (int i = threadIdx.x; i < 4096; i += 256){
    int cin = i >> 6, oc = i & 63;
    int h = cin >> 3, e = cin & 7;
    float s = 0.f;
#pragma unroll
    for (int dd = 0; dd < 8; dd++)
      s = fmaf(attn_s[(h*8 + dd)*8 + e], wps[(h*8 + dd)*64 + oc], s);
    g_Weff[b*4096 + i] = s;
  }
}

// ---- BN2 + residual + NCHW out + pooled sums ----
__global__ void k_bn2_add_pool(const float* __restrict__ x_orig, float* __restrict__ out,
                               const float* __restrict__ g2, const float* __restrict__ b2){
  int b = blockIdx.x, n0 = blockIdx.y * 64;
  __shared__ float s[64*65];
  __shared__ float scale[64], shift[64];
  if (threadIdx.x < 64){
    int c = threadIdx.x;
    float m   = g_stats[128 + c] * (1.f/CNT);
    float var = g_stats[192 + c] * (1.f/CNT) - m*m;
    float sc  = g2[c] * rsqrtf(var + 1e-4f);
    scale[c] = sc; shift[c] = b2[c] - m*sc;
  }
  const float* R = g_V + ((size_t)b*TOK + n0)*CH_;
  for (int idx = threadIdx.x; idx < 4096; idx += 256){
    int t = idx >> 6, c = idx & 63;
    s[t*65 + c] = R[idx];
  }
  __syncthreads();
  int y = n0 >> 7, x0 = n0 & 127;
  int iblk = y >> 4, jbase = x0 >> 4;
  const float* xb = x_orig + (size_t)b*CH_*TOK;
  float* ob = out + (size_t)b*CH_*TOK;
  for (int idx = threadIdx.x; idx < 4096; idx += 256){
    int c = idx >> 6, j = idx & 63;
    float f = leaky(s[j*65 + c]) * scale[c] + shift[c];
    size_t off = (size_t)c*TOK + n0 + j;
    float sval = f + xb[off];
    ob[off] = sval;
    float r = sval;
    r += __shfl_down_sync(0xffffffffu, r, 8, 16);
    r += __shfl_down_sync(0xffffffffu, r, 4, 16);
    r += __shfl_down_sync(0xffffffffu, r, 2, 16);
    r += __shfl_down_sync(0xffffffffu, r, 1, 16);
    if ((threadIdx.x & 15) == 0)
      atomicAdd(&g_pooled[(b*64 + c)*64 + iblk*8 + jbase + (j >> 4)], r);
  }
}

__global__ void k_minmax(){
  float mn = 3.4e38f, mx = -3.4e38f;
  for (int i = threadIdx.x; i < B_*4096; i += 1024){
    float v = g_pooled[i] * (1.f/256.f);
    mn = fminf(mn, v); mx = fmaxf(mx, v);
  }
#pragma unroll
  for (int o = 16; o > 0; o >>= 1){
    mn = fminf(mn, __shfl_xor_sync(0xffffffffu, mn, o));
    mx = fmaxf(mx, __shfl_xor_sync(0xffffffffu, mx, o));
  }
  __shared__ float smn[32], smx[32];
  if ((threadIdx.x & 31) == 0){ smn[threadIdx.x >> 5] = mn; smx[threadIdx.x >> 5] = mx; }
  __syncthreads();
  if (threadIdx.x < 32){
    mn = smn[threadIdx.x]; mx = smx[threadIdx.x];
#pragma unroll
    for (int o = 16; o > 0; o >>= 1){
      mn = fminf(mn, __shfl_xor_sync(0xffffffffu, mn, o));
      mx = fmaxf(mx, __shfl_xor_sync(0xffffffffu, mx, o));
    }
    if (threadIdx.x == 0){ g_minmax[0] = mn; g_minmax[1] = mx; }
  }
}

__global__ void k_gate(const float* __restrict__ w1, const float* __restrict__ w2){
  int b = blockIdx.x;
  __shared__ float y[4096];
  __shared__ float S[64];
  __shared__ float g0[64];
  __shared__ float hid[4];
  float mn = g_minmax[0];
  float inv = 1.f / (g_minmax[1] - mn);
  for (int i = threadIdx.x; i < 4096; i += 64)
    y[i] = (g_pooled[b*4096 + i] * (1.f/256.f) - mn) * inv;
  __syncthreads();
  {
    int i = threadIdx.x; float s = 0.f;
    for (int c = 0; c < 64; c++) s += y[c*64 + i];
    S[i] = s;
  }
  __syncthreads();
  {
    int c = threadIdx.x; float s = 0.f, sm2 = 0.f;
    for (int i = 0; i < 64; i++){
      s = fmaf(y[c*64 + i], S[i], s);
      sm2 += g_pooled[b*4096 + c*64 + i];
    }
    g0[c] = (s * (1.f/64.f)) * (sm2 * (1.f/16384.f));
  }
  __syncthreads();
  if (threadIdx.x < 4){
    int j = threadIdx.x; float h = 0.f;
    for (int c = 0; c < 64; c++) h = fmaf(g0[c], w1[c*4 + j], h);
    hid[j] = leaky(h);
  }
  __syncthreads();
  {
    int c = threadIdx.x; float o = 0.f;
#pragma unroll
    for (int j = 0; j < 4; j++) o = fmaf(hid[j], w2[j*64 + c], o);
    g_gate[b*64 + c] = 1.f / (1.f + expf(-o));
  }
}

// ---------------- d_out *= gate (float4) ----------------
__global__ void k_scale(float* __restrict__ out){
  size_t i4 = (size_t)blockIdx.x * 256 + threadIdx.x;   // float4 index
  float g = g_gate[i4 >> 12];                           // (i4*4) >> 14
  float4* o4 = (float4*)out;
  float4 v = o4[i4];
  v.x *= g; v.y *= g; v.z *= g; v.w *= g;
  o4[i4] = v;
}

// ================================ launch ========================================
extern "C" void kernel_launch(void* const* d_in, const int* in_sizes, int n_in,
                              void* d_out, int out_size){
  const float* x     = (const float*)d_in[0];
  const float* wq    = (const float*)d_in[1];
  const float* wk    = (const float*)d_in[2];
  const float* wv    = (const float*)d_in[3];
  const float* wproj = (const float*)d_in[4];
  const float* bproj = (const float*)d_in[5];
  const float* wpos  = (const float*)d_in[6];
  const float* ln_g  = (const float*)d_in[7];
  const float* ln_b  = (const float*)d_in[8];
  const float* wff   = (const float*)d_in[9];
  const float* bn1_g = (const float*)d_in[10];
  const float* bn1_b = (const float*)d_in[11];
  const float* wd    = (const float*)d_in[12];
  const float* bn2_g = (const float*)d_in[13];
  const float* bn2_b = (const float*)d_in[14];
  const float* sw1   = (const float*)d_in[15];
  const float* sw2   = (const float*)d_in[16];
  float* out = (float*)d_out;

  cudaFuncSetAttribute(k_gemm<0>,    cudaFuncAttributeMaxDynamicSharedMemorySize, SM_GEMM_BYTES);
  cudaFuncSetAttribute(k_gemm<3>,    cudaFuncAttributeMaxDynamicSharedMemorySize, SM_GEMM_BYTES);
  cudaFuncSetAttribute(k_fused12<0>, cudaFuncAttributeMaxDynamicSharedMemorySize, SM_F_BYTES);
  cudaFuncSetAttribute(k_fused12<1>, cudaFuncAttributeMaxDynamicSharedMemorySize, SM_F_BYTES);
  cudaFuncSetAttribute(k_attn_weff,  cudaFuncAttributeMaxDynamicSharedMemorySize, 100*1024);

  void *pC = nullptr, *pStats = nullptr, *pPooled = nullptr;
  cudaGetSymbolAddress(&pC, g_C);
  cudaGetSymbolAddress(&pStats, g_stats);
  cudaGetSymbolAddress(&pPooled, g_pooled);

  cudaMemsetAsync(pStats, 0, 256*sizeof(float));
  k_transpose_in<<<dim3(16, 256), 256>>>(x);
  for (int l = 0; l < 2; l++){
    cudaMemsetAsync(pC, 0, 16*4096*sizeof(float));
    k_gemm<0><<<dim3(16, 128), 256, SM_GEMM_BYTES>>>(wv + l*4096, nullptr, nullptr);
    k_attn_weff<<<16, 256, 6*4096*sizeof(float)>>>(wq + l*4096, wk + l*4096, wproj + l*4096);
    if (l == 0)
      k_fused12<0><<<dim3(16, 128), 256, SM_F_BYTES>>>(wff + l*4096, bproj + l*64, ln_g + l*64, ln_b + l*64, wpos + l*576);
    else
      k_fused12<1><<<dim3(16, 128), 256, SM_F_BYTES>>>(wff + l*4096, bproj + l*64, ln_g + l*64, ln_b + l*64, wpos + l*576);
  }
  k_gemm<3><<<dim3(16, 128), 256, SM_GEMM_BYTES>>>(wd, bn1_g, bn1_b);
  cudaMemsetAsync(pPooled, 0, 16*4096*sizeof(float));
  k_bn2_add_pool<<<dim3(16, 256), 256>>>(x, out, bn2_g, bn2_b);
  k_minmax<<<1, 1024>>>();
  k_gate<<<16, 64>>>(sw1, sw2);
  k_scale<<<16384, 256>>>(out);
}